// round 6
// baseline (speedup 1.0000x reference)
#include <cuda_runtime.h>

#define N 8192
#define D 256
#define NC 10
#define NP 5               // class pairs
#define GRID 256
#define BLOCK 512
#define RPB (N / GRID)     // 32 rows per block
#define RPT (RPB / 2)      // 16 rows per thread (2 row sub-groups)

// PAR = COV * 0.5 / BATCH_SIZE = 0.5 / 8192
#define PARF 6.103515625e-05

// Global accumulators. Statically zero-initialized; the finishing block
// resets them after consuming, so every launch / graph replay sees zeros.
__device__ float4 g_pack[NP][D];   // {v_{2p}, q_{2p}, v_{2p+1}, q_{2p+1}} per column
__device__ int    g_cnt[NC];
__device__ unsigned int g_done;

__device__ __forceinline__ void red_add_v4(float4* addr, float4 v) {
    asm volatile("red.global.add.v4.f32 [%0], {%1, %2, %3, %4};"
                 :: "l"(addr), "f"(v.x), "f"(v.y), "f"(v.z), "f"(v.w)
                 : "memory");
}

__global__ __launch_bounds__(BLOCK) void fused_kernel(const float* __restrict__ out,
                                                      const int* __restrict__ label,
                                                      float* __restrict__ res) {
    // Two replicas (one per row sub-group) double as the chain-splitting parity.
    __shared__ float2 svq[2][NC][D];     // 40 KB
    __shared__ int    s_lab[RPB];
    __shared__ int    scnt[NC];
    __shared__ int    s_last;
    __shared__ double red[D];

    int t   = threadIdx.x;
    int col = t & (D - 1);     // 0..255
    int sub = t >> 8;          // 0 or 1: which 16-row half
    int r0  = blockIdx.x * RPB;

    #pragma unroll
    for (int c = 0; c < NC; c++)
        svq[sub][c][col] = make_float2(0.f, 0.f);
    if (t < NC) scnt[t] = 0;
    if (t < RPB) s_lab[t] = label[r0 + t];
    __syncthreads();

    if (t < RPB) atomicAdd(&scnt[s_lab[t]], 1);

    // ---- accumulate: 16 rows per thread, column `col` ----
    int rbase = r0 + sub * RPT;
    #pragma unroll 8
    for (int i = 0; i < RPT; i++) {
        float x = out[(size_t)(rbase + i) * D + col];
        int   l = s_lab[sub * RPT + i];     // uniform across each half
        float2 a = svq[sub][l][col];
        a.x += x;
        a.y += x * x;
        svq[sub][l][col] = a;
    }
    __syncthreads();

    // ---- flush: half the threads combine replicas, 5 vector REDs each ----
    if (t < D) {
        #pragma unroll
        for (int p = 0; p < NP; p++) {
            int c0 = 2 * p, c1 = 2 * p + 1;
            float2 a0 = svq[0][c0][t], b0 = svq[1][c0][t];
            float2 a1 = svq[0][c1][t], b1 = svq[1][c1][t];
            red_add_v4(&g_pack[p][t],
                       make_float4(a0.x + b0.x, a0.y + b0.y,
                                   a1.x + b1.x, a1.y + b1.y));
        }
    }
    if (t < NC && scnt[t]) atomicAdd(&g_cnt[t], scnt[t]);

    // ---- last-block-arrival handoff ----
    __threadfence();
    __syncthreads();
    if (t == 0) {
        unsigned int prev = atomicAdd(&g_done, 1u);
        s_last = (prev == GRID - 1);
    }
    __syncthreads();
    if (!s_last) return;

    // =================== finish phase (one block) ===================
    __threadfence();   // acquire side of the counter handshake

    __shared__ int cnt[NC];
    if (t < NC) { cnt[t] = g_cnt[t]; g_cnt[t] = 0; }
    if (t == 0) g_done = 0;
    __syncthreads();

    if (t < D) {
        int l0 = label[0];
        int lL = label[N - 1];
        // Row set A = [0, N-1) excludes row N-1; B = [1, N) excludes row 0.
        float x0 = out[t];                        // row 0,   column t
        float xL = out[(size_t)(N - 1) * D + t];  // row N-1, column t

        float eqp = 0.f;           // per-column contribution to T_eq
        float uA = 0.f, uB = 0.f;  // column sums over all classes (for T_all)
        float qa = 0.f, qb = 0.f;  // column square-sums over all classes

        #pragma unroll
        for (int p = 0; p < NP; p++) {
            float4 vq = g_pack[p][t];
            g_pack[p][t] = make_float4(0.f, 0.f, 0.f, 0.f);   // consume + reset
            #pragma unroll
            for (int h = 0; h < 2; h++) {
                int   c = 2 * p + h;
                float v = h ? vq.z : vq.x;
                float q = h ? vq.w : vq.y;
                float vA = v - ((lL == c) ? xL : 0.f);
                float vB = v - ((l0 == c) ? x0 : 0.f);
                float qA = q - ((lL == c) ? xL * xL : 0.f);
                float qB = q - ((l0 == c) ? x0 * x0 : 0.f);
                float nA = (float)(cnt[c] - (lL == c));
                float nB = (float)(cnt[c] - (l0 == c));
                // T_eq = sum_c [ nB*S_c^A + nA*S_c^B - 2 * vA . vB ]
                eqp += nB * qA + nA * qB - 2.f * vA * vB;
                uA += vA; uB += vB; qa += qA; qb += qB;
            }
        }

        // T_all = (N-1)*(S_A + S_B) - 2 * uA . uB   (per-column slice)
        double allp = (double)(N - 1) * ((double)qa + (double)qb)
                    - 2.0 * (double)uA * (double)uB;
        red[t] = 2.0 * (double)eqp - allp;
    }
    __syncthreads();

    #pragma unroll
    for (int s = D / 2; s > 0; s >>= 1) {
        if (t < s) red[t] += red[t + s];
        __syncthreads();
    }
    if (t == 0) res[0] = (float)(PARF * red[0]);
}

extern "C" void kernel_launch(void* const* d_in, const int* in_sizes, int n_in,
                              void* d_out, int out_size) {
    const float* out   = (const float*)d_in[0];
    const int*   label = (const int*)d_in[1];
    fused_kernel<<<GRID, BLOCK>>>(out, label, (float*)d_out);
}